// round 1
// baseline (speedup 1.0000x reference)
#include <cuda_runtime.h>
#include <cstdint>

// ---------------- problem constants ----------------
#define Gn    4
#define Bsz   8
#define HIN   128
#define HD    2324
#define NW    36864
#define NB    64
#define NWB   36928          // NW + NB
#define NWB4  9232           // NWB / 4
#define GIN   64
#define GOUT  64
#define HWIMG 64

typedef unsigned long long ull;

// ---------------- scratch (device globals; no allocs allowed) ----------------
__device__ float g_h[Gn * HD * Bsz];          // h transposed: [g][d][b]
__device__ float g_gened[(size_t)Gn * Bsz * NWB];  // [g][b][o]

// ---------------- packed fp32x2 helpers (Blackwell FFMA2) ----------------
__device__ __forceinline__ ull pack2(float lo, float hi) {
    ull r; asm("mov.b64 %0, {%1, %2};" : "=l"(r) : "f"(lo), "f"(hi)); return r;
}
__device__ __forceinline__ void fma2(ull& d, ull a, ull b) {
    asm("fma.rn.f32x2 %0, %1, %2, %0;" : "+l"(d) : "l"(a), "l"(b));
}
__device__ __forceinline__ float2 unpack2(ull v) {
    float2 r; asm("mov.b64 {%0, %1}, %2;" : "=f"(r.x), "=f"(r.y) : "l"(v)); return r;
}

// ============================================================================
// Kernel 1: h[g][d][b] = relu(sum_i hyper[b][i] * W1[g][i][d] + b1[g][d])
// Tiny (19 MFLOP). One thread per (g,d), all 8 batches in registers.
// ============================================================================
__global__ __launch_bounds__(256) void mlp1_kernel(
    const float* __restrict__ hyper,   // [B][HIN]
    const float* __restrict__ W1,      // [G][HIN][HD]
    const float* __restrict__ b1)      // [G][HD]
{
    __shared__ float sh[Bsz * HIN];
    const int g = blockIdx.y;
    const int tid = threadIdx.x;
    for (int i = tid; i < Bsz * HIN; i += 256) sh[i] = hyper[i];
    __syncthreads();

    const int d = blockIdx.x * 256 + tid;
    if (d >= HD) return;

    float acc[Bsz];
    const float bv = b1[g * HD + d];
#pragma unroll
    for (int b = 0; b < Bsz; b++) acc[b] = bv;

    const float* w1p = W1 + (size_t)g * HIN * HD + d;
#pragma unroll 4
    for (int i = 0; i < HIN; i++) {
        const float w = w1p[(size_t)i * HD];   // coalesced over d
#pragma unroll
        for (int b = 0; b < Bsz; b++) acc[b] = fmaf(sh[b * HIN + i], w, acc[b]);
    }

    float* hp = g_h + ((size_t)g * HD + d) * Bsz;
#pragma unroll
    for (int b = 0; b < Bsz; b++) hp[b] = fmaxf(acc[b], 0.0f);
}

// ============================================================================
// Kernel 2: gened[g][b][o] = sum_d h[g][d][b] * W2[g][d][o] + b2[g][o]
// HBM-bound on the 1.37 GB one-pass read of W2. Each thread: 4 columns x
// 8 batches. Batch pairs packed into f32x2 accumulators; W2 via __ldcs
// float4; manual unroll-4 for memory-level parallelism.
// ============================================================================
__global__ __launch_bounds__(256) void mlp2_kernel(
    const float* __restrict__ W2,      // [G][HD][NWB]
    const float* __restrict__ b2)      // [G][NWB]
{
    const int g = blockIdx.y;
    const int o4 = blockIdx.x * 256 + threadIdx.x;   // float4 column index
    if (o4 >= NWB4) return;

    ull acc[4][4];   // [col j][batch-pair bp]
#pragma unroll
    for (int j = 0; j < 4; j++)
#pragma unroll
        for (int bp = 0; bp < 4; bp++) acc[j][bp] = 0ull;

    const float4*  w2p = reinterpret_cast<const float4*>(W2 + (size_t)g * HD * NWB);
    const double2* hp  = reinterpret_cast<const double2*>(g_h + (size_t)g * HD * Bsz);

    for (int d0 = 0; d0 < HD; d0 += 4) {     // HD % 4 == 0
        float4  w[4];
        double2 h0[4], h1[4];
#pragma unroll
        for (int u = 0; u < 4; u++) {        // batch loads -> MLP
            w[u]  = __ldcs(w2p + (size_t)(d0 + u) * NWB4 + o4);
            h0[u] = __ldg(hp + (size_t)(d0 + u) * 2);
            h1[u] = __ldg(hp + (size_t)(d0 + u) * 2 + 1);
        }
#pragma unroll
        for (int u = 0; u < 4; u++) {
            ull hb[4];
            hb[0] = __double_as_longlong(h0[u].x);   // (b0,b1)
            hb[1] = __double_as_longlong(h0[u].y);   // (b2,b3)
            hb[2] = __double_as_longlong(h1[u].x);   // (b4,b5)
            hb[3] = __double_as_longlong(h1[u].y);   // (b6,b7)
            ull wj[4];
            wj[0] = pack2(w[u].x, w[u].x);
            wj[1] = pack2(w[u].y, w[u].y);
            wj[2] = pack2(w[u].z, w[u].z);
            wj[3] = pack2(w[u].w, w[u].w);
#pragma unroll
            for (int j = 0; j < 4; j++)
#pragma unroll
                for (int bp = 0; bp < 4; bp++)
                    fma2(acc[j][bp], wj[j], hb[bp]);
        }
    }

    const float4 bv = __ldg(reinterpret_cast<const float4*>(b2 + (size_t)g * NWB) + o4);
#pragma unroll
    for (int bp = 0; bp < 4; bp++) {
        const float2 c0 = unpack2(acc[0][bp]);
        const float2 c1 = unpack2(acc[1][bp]);
        const float2 c2 = unpack2(acc[2][bp]);
        const float2 c3 = unpack2(acc[3][bp]);
        float4* dst0 = reinterpret_cast<float4*>(g_gened + (size_t)(g * Bsz + 2 * bp) * NWB) + o4;
        float4* dst1 = reinterpret_cast<float4*>(g_gened + (size_t)(g * Bsz + 2 * bp + 1) * NWB) + o4;
        *dst0 = make_float4(c0.x + bv.x, c1.x + bv.y, c2.x + bv.z, c3.x + bv.w);
        *dst1 = make_float4(c0.y + bv.x, c1.y + bv.y, c2.y + bv.z, c3.y + bv.w);
    }
}

// ============================================================================
// Kernel 3: dynamic grouped 3x3 conv (pad=1).
// out[b][g*64+oc][y][x] = sum_{c,p} w[g][b][oc][c*9+p] * img[b][g*64+c][y+dy-1][x+dx-1]
//                         + bias[g][b][oc]
// Block = (strip of 4 rows x 64 cols, g, b). 256 threads.
// Thread: 8 out-channels (ty*8..) x 8 pixels (i*32+tx). Accumulators packed
// over oc-pairs so the weight operand is a direct LDS.64 (no pack); only the
// image value needs a duplicate pack2. 52 instr per 64 FMA.
// ============================================================================
#define WS_LD 66   // padded row (even -> keeps LDS.64 alignment, kills 32-way STS conflict)

__global__ __launch_bounds__(256, 2) void conv_kernel(
    const float* __restrict__ image,   // [B][256][64][64]
    float* __restrict__ out)           // [B][256][64][64]
{
    __shared__ float img_s[8 * 6 * 68];     // 8 ch x 6 rows x cols(-1..64 stored at +1)
    __shared__ float w_s[72 * WS_LD];       // [kk][oc] transposed weight chunk

    const int strip = blockIdx.x;   // 0..15 -> rows y0..y0+3
    const int g = blockIdx.y;
    const int b = blockIdx.z;
    const int tid = threadIdx.x;
    const int tx = tid & 31;
    const int ty = tid >> 5;        // oc base = ty*8
    const int y0 = strip * 4;

    const float* gw = g_gened + (size_t)(g * Bsz + b) * NWB;
    const float* img_base = image + (size_t)(b * 256 + g * 64) * 64 * 64;

    ull acc[4][8];   // [oc-pair j][pixel i]
#pragma unroll
    for (int j = 0; j < 4; j++)
#pragma unroll
        for (int i = 0; i < 8; i++) acc[j][i] = 0ull;

#pragma unroll 1
    for (int cc = 0; cc < 8; cc++) {        // 8 input-channel chunks of 8
        __syncthreads();
        // ---- stage image chunk: ch cc*8..+7, rows y0-1..y0+4, cols -1..64 ----
        for (int idx = tid; idx < 8 * 6 * 66; idx += 256) {
            const int c   = idx / (6 * 66);
            const int rem = idx % (6 * 66);
            const int r   = rem / 66;
            const int col = rem % 66;       // stored col = real col + 1
            const int yy  = y0 - 1 + r;
            const int xx  = col - 1;
            float v = 0.0f;
            if (yy >= 0 && yy < 64 && xx >= 0 && xx < 64)
                v = img_base[((size_t)(cc * 8 + c) * 64 + yy) * 64 + xx];
            img_s[(c * 6 + r) * 68 + col] = v;
        }
        // ---- stage transposed weight chunk: w_s[kk][oc] = gw[oc*576 + cc*72 + kk] ----
        for (int idx = tid; idx < 72 * 64; idx += 256) {
            const int oc = idx / 72;
            const int kk = idx % 72;        // coalesced global read along kk
            w_s[kk * WS_LD + oc] = gw[oc * 576 + cc * 72 + kk];
        }
        __syncthreads();

        // ---- compute: 72 k-steps, 32 fma2 each ----
#pragma unroll 2
        for (int ic = 0; ic < 8; ic++) {
#pragma unroll
            for (int p = 0; p < 9; p++) {
                const int kk = ic * 9 + p;
                const int dy = p / 3, dx = p % 3;
                ull wv[4];
#pragma unroll
                for (int j = 0; j < 4; j++)   // broadcast LDS.64 (oc pair)
                    wv[j] = *reinterpret_cast<const ull*>(&w_s[kk * WS_LD + ty * 8 + 2 * j]);
#pragma unroll
                for (int i = 0; i < 8; i++) {
                    const float v = img_s[(ic * 6 + (i >> 1) + dy) * 68 + (i & 1) * 32 + tx + dx];
                    const ull vv = pack2(v, v);
#pragma unroll
                    for (int j = 0; j < 4; j++) fma2(acc[j][i], wv[j], vv);
                }
            }
        }
    }

    // ---- bias + writeout (coalesced per (oc,row): lanes span 32 consecutive x) ----
    float bias[8];
#pragma unroll
    for (int j = 0; j < 8; j++) bias[j] = gw[NW + ty * 8 + j];

#pragma unroll
    for (int j = 0; j < 4; j++) {
        const int oc0 = ty * 8 + 2 * j;
#pragma unroll
        for (int i = 0; i < 8; i++) {
            const float2 r  = unpack2(acc[j][i]);
            const int yi = i >> 1;
            const int xi = (i & 1) * 32 + tx;
            const size_t base = ((size_t)(b * 256 + g * 64 + oc0) * 64 + (y0 + yi)) * 64 + xi;
            out[base]        = r.x + bias[2 * j];
            out[base + 4096] = r.y + bias[2 * j + 1];
        }
    }
}

// ============================================================================
// launch
// ============================================================================
extern "C" void kernel_launch(void* const* d_in, const int* in_sizes, int n_in,
                              void* d_out, int out_size) {
    const float* image = (const float*)d_in[0];
    const float* hyper = (const float*)d_in[1];
    const float* W1    = (const float*)d_in[2];
    const float* b1    = (const float*)d_in[3];
    const float* W2    = (const float*)d_in[4];
    const float* b2    = (const float*)d_in[5];
    float* out = (float*)d_out;

    mlp1_kernel<<<dim3(10, Gn), 256>>>(hyper, W1, b1);        // ceil(2324/256)=10
    mlp2_kernel<<<dim3(37, Gn), 256>>>(W2, b2);               // ceil(9232/256)=37
    conv_kernel<<<dim3(16, Gn, Bsz), 256>>>(image, out);      // 16 strips x 4 g x 8 b
}

// round 6
// speedup vs baseline: 1.4053x; 1.4053x over previous
#include <cuda_runtime.h>
#include <cstdint>

// ---------------- problem constants ----------------
#define Gn    4
#define Bsz   8
#define HIN   128
#define HD    2324
#define HD_SPLIT 1164        // split point: 1164 and 1160, both %4==0
#define NW    36864
#define NB    64
#define NWB   36928          // NW + NB
#define NWB4  9232           // NWB / 4

typedef unsigned long long ull;

// ---------------- scratch (device globals; no allocs allowed) ----------------
__device__ float g_h[Gn * HD * Bsz];                    // h transposed: [g][d][b]
__device__ float g_part[2ULL * Gn * Bsz * NWB];         // split-K partials [s][g][b][o]

// ---------------- packed fp32x2 helpers (Blackwell FFMA2) ----------------
__device__ __forceinline__ ull pack2(float lo, float hi) {
    ull r; asm("mov.b64 %0, {%1, %2};" : "=l"(r) : "f"(lo), "f"(hi)); return r;
}
__device__ __forceinline__ void fma2(ull& d, ull a, ull b) {
    asm("fma.rn.f32x2 %0, %1, %2, %0;" : "+l"(d) : "l"(a), "l"(b));
}
__device__ __forceinline__ float2 unpack2(ull v) {
    float2 r; asm("mov.b64 {%0, %1}, %2;" : "=f"(r.x), "=f"(r.y) : "l"(v)); return r;
}

// dummy launch to align ncu's fixed capture index onto mlp2
__global__ void noop_kernel() {}

// ============================================================================
// Kernel 1: h[g][d][b] = relu(sum_i hyper[b][i] * W1[g][i][d] + b1[g][d])
// Batch-split x4 for parallelism: grid (10, G, 4), thread = (d, 2 batches).
// ============================================================================
__global__ __launch_bounds__(256) void mlp1_kernel(
    const float* __restrict__ hyper,   // [B][HIN]
    const float* __restrict__ W1,      // [G][HIN][HD]
    const float* __restrict__ b1)      // [G][HD]
{
    __shared__ float sh[2 * HIN];
    const int g  = blockIdx.y;
    const int bz = blockIdx.z;          // batch pair: b = bz*2 + {0,1}
    const int tid = threadIdx.x;
    for (int i = tid; i < 2 * HIN; i += 256) sh[i] = hyper[bz * 2 * HIN + i];
    __syncthreads();

    const int d = blockIdx.x * 256 + tid;
    if (d >= HD) return;

    const float bv = b1[g * HD + d];
    float a0 = bv, a1 = bv;

    const float* w1p = W1 + (size_t)g * HIN * HD + d;
#pragma unroll 4
    for (int i = 0; i < HIN; i++) {
        const float w = w1p[(size_t)i * HD];   // coalesced over d
        a0 = fmaf(sh[i], w, a0);
        a1 = fmaf(sh[HIN + i], w, a1);
    }

    float* hp = g_h + ((size_t)g * HD + d) * Bsz + bz * 2;
    hp[0] = fmaxf(a0, 0.0f);
    hp[1] = fmaxf(a1, 0.0f);
}

// ============================================================================
// Kernel 2: split-K over HD. partial[s][g][b][o] = sum_{d in half s} h*W2
// (+ b2 folded into s==0). 296 blocks -> 2 blocks/SM -> ~32KB LDG in flight
// per SM, above the ~18KB latency-BW product. HBM-bound on W2 (1.37 GB).
// ============================================================================
__global__ __launch_bounds__(256) void mlp2_kernel(
    const float* __restrict__ W2,      // [G][HD][NWB]
    const float* __restrict__ b2)      // [G][NWB]
{
    const int g = blockIdx.y;
    const int s = blockIdx.z;
    const int o4 = blockIdx.x * 256 + threadIdx.x;   // float4 column index
    if (o4 >= NWB4) return;

    const int d_begin = s ? HD_SPLIT : 0;
    const int d_end   = s ? HD       : HD_SPLIT;

    ull acc[4][4];   // [col j][batch-pair bp]
#pragma unroll
    for (int j = 0; j < 4; j++)
#pragma unroll
        for (int bp = 0; bp < 4; bp++) acc[j][bp] = 0ull;

    const float4*  w2p = reinterpret_cast<const float4*>(W2 + (size_t)g * HD * NWB);
    const double2* hp  = reinterpret_cast<const double2*>(g_h + (size_t)g * HD * Bsz);

    for (int d0 = d_begin; d0 < d_end; d0 += 4) {
        float4  w[4];
        double2 h0[4], h1[4];
#pragma unroll
        for (int u = 0; u < 4; u++) {        // batch loads -> MLP
            w[u]  = __ldcs(w2p + (size_t)(d0 + u) * NWB4 + o4);
            h0[u] = __ldg(hp + (size_t)(d0 + u) * 2);
            h1[u] = __ldg(hp + (size_t)(d0 + u) * 2 + 1);
        }
#pragma unroll
        for (int u = 0; u < 4; u++) {
            ull hb[4];
            hb[0] = __double_as_longlong(h0[u].x);   // (b0,b1)
            hb[1] = __double_as_longlong(h0[u].y);   // (b2,b3)
            hb[2] = __double_as_longlong(h1[u].x);   // (b4,b5)
            hb[3] = __double_as_longlong(h1[u].y);   // (b6,b7)
            ull wj[4];
            wj[0] = pack2(w[u].x, w[u].x);
            wj[1] = pack2(w[u].y, w[u].y);
            wj[2] = pack2(w[u].z, w[u].z);
            wj[3] = pack2(w[u].w, w[u].w);
#pragma unroll
            for (int j = 0; j < 4; j++)
#pragma unroll
                for (int bp = 0; bp < 4; bp++)
                    fma2(acc[j][bp], wj[j], hb[bp]);
        }
    }

    float4 bv = make_float4(0.f, 0.f, 0.f, 0.f);
    if (s == 0)
        bv = __ldg(reinterpret_cast<const float4*>(b2 + (size_t)g * NWB) + o4);

    float* base = g_part + ((size_t)(s * Gn + g) * Bsz) * NWB;
#pragma unroll
    for (int bp = 0; bp < 4; bp++) {
        const float2 c0 = unpack2(acc[0][bp]);
        const float2 c1 = unpack2(acc[1][bp]);
        const float2 c2 = unpack2(acc[2][bp]);
        const float2 c3 = unpack2(acc[3][bp]);
        float4* dst0 = reinterpret_cast<float4*>(base + (size_t)(2 * bp) * NWB) + o4;
        float4* dst1 = reinterpret_cast<float4*>(base + (size_t)(2 * bp + 1) * NWB) + o4;
        *dst0 = make_float4(c0.x + bv.x, c1.x + bv.y, c2.x + bv.z, c3.x + bv.w);
        *dst1 = make_float4(c0.y + bv.x, c1.y + bv.y, c2.y + bv.z, c3.y + bv.w);
    }
}

// ============================================================================
// Kernel 3: dynamic grouped 3x3 conv (pad=1), split-K partials summed during
// weight staging. Block = (4-row strip, g, b). 256 threads.
// Thread tile: 16 out-channels (8 f32x2 pairs) x 4 pixels (one column, 4 rows).
// Per k-step: 8 broadcast LDS.64 (weights) + 4 LDS.32 (img) + 4 pack + 32 fma2
// = 52 issue slots vs 64 fma-pipe cycles -> fma-bound.
// ============================================================================
#define WS_LD 66   // padded w_s row (gcd(66,32)=2 -> only 2-way STS conflict)

__global__ __launch_bounds__(256, 2) void conv_kernel(
    const float* __restrict__ image,   // [B][256][64][64]
    float* __restrict__ out)           // [B][256][64][64]
{
    __shared__ __align__(16) float img_s[8 * 6 * 68];  // 8 ch x 6 rows x cols(-1..64 @ +1)
    __shared__ __align__(16) float w_s[72 * WS_LD];    // [kk][oc] transposed weight chunk

    const int strip = blockIdx.x;   // 0..15 -> rows y0..y0+3
    const int g = blockIdx.y;
    const int b = blockIdx.z;
    const int tid = threadIdx.x;
    const int pid = tid & 63;       // output column 0..63
    const int ocg = tid >> 6;       // oc base = ocg*16
    const int y0 = strip * 4;

    const float* gw0 = g_part + ((size_t)(0 * Gn + g) * Bsz + b) * NWB;
    const float* gw1 = g_part + ((size_t)(1 * Gn + g) * Bsz + b) * NWB;
    const float* img_base = image + (size_t)(b * 256 + g * 64) * 64 * 64;

    ull acc[8][4];   // [oc-pair j][row r]
#pragma unroll
    for (int j = 0; j < 8; j++)
#pragma unroll
        for (int r = 0; r < 4; r++) acc[j][r] = 0ull;

#pragma unroll 1
    for (int cc = 0; cc < 8; cc++) {        // 8 input-channel chunks of 8
        __syncthreads();
        // ---- stage image chunk: ch cc*8..+7, rows y0-1..y0+4, cols -1..64 ----
        for (int idx = tid; idx < 8 * 6 * 66; idx += 256) {
            const int c   = idx / (6 * 66);
            const int rem = idx % (6 * 66);
            const int rr  = rem / 66;
            const int col = rem % 66;       // stored col = real col + 1
            const int yy  = y0 - 1 + rr;
            const int xx  = col - 1;
            float v = 0.0f;
            if (yy >= 0 && yy < 64 && xx >= 0 && xx < 64)
                v = __ldg(&img_base[((size_t)(cc * 8 + c) * 64 + yy) * 64 + xx]);
            img_s[(c * 6 + rr) * 68 + col] = v;
        }
        // ---- stage transposed weight chunk, summing split-K partials ----
        for (int idx = tid; idx < 72 * 64; idx += 256) {
            const int oc = idx / 72;
            const int kk = idx % 72;        // coalesced global read along kk
            const int gi = oc * 576 + cc * 72 + kk;
            w_s[kk * WS_LD + oc] = __ldg(&gw0[gi]) + __ldg(&gw1[gi]);
        }
        __syncthreads();

        // ---- compute: 72 k-steps, 32 fma2 each ----
#pragma unroll 2
        for (int ic = 0; ic < 8; ic++) {
#pragma unroll
            for (int p = 0; p < 9; p++) {
                const int kk = ic * 9 + p;
                const int dy = p / 3, dx = p % 3;
                ull vv[4];
#pragma unroll
                for (int r = 0; r < 4; r++) {
                    const float v = img_s[(ic * 6 + r + dy) * 68 + pid + dx];
                    vv[r] = pack2(v, v);
                }
#pragma unroll
                for (int j = 0; j < 8; j++) {
                    const ull wv = *reinterpret_cast<const ull*>(
                        &w_s[kk * WS_LD + ocg * 16 + 2 * j]);   // warp-broadcast LDS.64
#pragma unroll
                    for (int r = 0; r < 4; r++) fma2(acc[j][r], wv, vv[r]);
                }
            }
        }
    }

    // ---- bias (sum partials) + writeout: lanes span 64 consecutive x ----
    float bias[16];
#pragma unroll
    for (int j = 0; j < 16; j++) {
        const int oc = ocg * 16 + j;
        bias[j] = gw0[NW + oc] + gw1[NW + oc];
    }

#pragma unroll
    for (int j = 0; j < 8; j++) {
        const int oc0 = ocg * 16 + 2 * j;
#pragma unroll
        for (int r = 0; r < 4; r++) {
            const float2 rv = unpack2(acc[j][r]);
            const size_t base = ((size_t)(b * 256 + g * 64 + oc0) * 64 + (y0 + r)) * 64 + pid;
            out[base]        = rv.x + bias[2 * j];
            out[base + 4096] = rv.y + bias[2 * j + 1];
        }
    }
}

// ============================================================================
// launch
// ============================================================================
extern "C" void kernel_launch(void* const* d_in, const int* in_sizes, int n_in,
                              void* d_out, int out_size) {
    const float* image = (const float*)d_in[0];
    const float* hyper = (const float*)d_in[1];
    const float* W1    = (const float*)d_in[2];
    const float* b1    = (const float*)d_in[3];
    const float* W2    = (const float*)d_in[4];
    const float* b2    = (const float*)d_in[5];
    float* out = (float*)d_out;

    noop_kernel<<<1, 32>>>();                                  // profile-index alignment
    mlp1_kernel<<<dim3(10, Gn, 4), 256>>>(hyper, W1, b1);      // ceil(2324/256)=10
    mlp2_kernel<<<dim3(37, Gn, 2), 256>>>(W2, b2);             // split-K x2
    conv_kernel<<<dim3(16, Gn, Bsz), 256>>>(image, out);       // 16 strips x 4 g x 8 b
}

// round 8
// speedup vs baseline: 1.6130x; 1.1478x over previous
#include <cuda_runtime.h>
#include <cstdint>

// ---------------- problem constants ----------------
#define Gn    4
#define Bsz   8
#define HIN   128
#define HD    2324
#define HD_SPLIT 1164        // halves 1164/1160, both %4==0
#define NW    36864
#define NB    64
#define NWB   36928          // NW + NB
#define NWB2  18464          // NWB / 2

// conv chunking: 16 chunks of 4 input channels
#define CCH   16
#define CPC   4
#define KKC   36             // CPC*9
#define IMG_BUF 1728         // CPC*6*72
#define W_BUF   2304         // KKC*64

typedef unsigned long long ull;

// ---------------- scratch (device globals; no allocs allowed) ----------------
__device__ float g_h[Gn * HD * Bsz];                    // h transposed: [g][d][b]
__device__ float g_part[2ULL * Gn * Bsz * NWB];         // split-K partials [s][g][b][o]
__device__ float g_w[(size_t)Gn * Bsz * CCH * W_BUF];   // transposed summed weights
__device__ float g_wb[Gn * Bsz * 64];                   // summed biases

// ---------------- packed fp32x2 helpers (Blackwell FFMA2) ----------------
__device__ __forceinline__ ull pack2(float lo, float hi) {
    ull r; asm("mov.b64 %0, {%1, %2};" : "=l"(r) : "f"(lo), "f"(hi)); return r;
}
__device__ __forceinline__ void fma2(ull& d, ull a, ull b) {
    asm("fma.rn.f32x2 %0, %1, %2, %0;" : "+l"(d) : "l"(a), "l"(b));
}
__device__ __forceinline__ float2 unpack2(ull v) {
    float2 r; asm("mov.b64 {%0, %1}, %2;" : "=f"(r.x), "=f"(r.y) : "l"(v)); return r;
}

// ---------------- cp.async helpers ----------------
__device__ __forceinline__ void cp16(uint32_t smem_addr, const void* gptr) {
    asm volatile("cp.async.cg.shared.global [%0], [%1], 16;"
                 :: "r"(smem_addr), "l"(gptr));
}
#define CP_COMMIT()  asm volatile("cp.async.commit_group;")
#define CP_WAIT(N)   asm volatile("cp.async.wait_group %0;" :: "n"(N))

// ncu captures absolute launch index 3 — shims place mlp2 there
__global__ void noop_kernel() {}

// ============================================================================
// Kernel 1: h[g][d][b] = relu(hyper @ W1 + b1). Grid (10, G, 4).
// ============================================================================
__global__ __launch_bounds__(256) void mlp1_kernel(
    const float* __restrict__ hyper, const float* __restrict__ W1,
    const float* __restrict__ b1)
{
    __shared__ float sh[2 * HIN];
    const int g  = blockIdx.y;
    const int bz = blockIdx.z;
    const int tid = threadIdx.x;
    for (int i = tid; i < 2 * HIN; i += 256) sh[i] = hyper[bz * 2 * HIN + i];
    __syncthreads();

    const int d = blockIdx.x * 256 + tid;
    if (d >= HD) return;

    const float bv = b1[g * HD + d];
    float a0 = bv, a1 = bv;
    const float* w1p = W1 + (size_t)g * HIN * HD + d;
#pragma unroll 4
    for (int i = 0; i < HIN; i++) {
        const float w = w1p[(size_t)i * HD];
        a0 = fmaf(sh[i], w, a0);
        a1 = fmaf(sh[HIN + i], w, a1);
    }
    float* hp = g_h + ((size_t)g * HD + d) * Bsz + bz * 2;
    hp[0] = fmaxf(a0, 0.0f);
    hp[1] = fmaxf(a1, 0.0f);
}

// ============================================================================
// Kernel 2: split-K x2 over HD, 2-column tile (acc 16 ull -> ~75 regs ->
// 3 CTAs/SM = 24 warps). Was latency-bound at 16 warps; 8 warps/SMSP now
// hide DRAM latency. partial[s][g][b][o] = sum_{d in half} h*W2 (+b2 @ s==0)
// ============================================================================
__global__ __launch_bounds__(256, 3) void mlp2_kernel(
    const float* __restrict__ W2, const float* __restrict__ b2)
{
    const int g = blockIdx.y;
    const int s = blockIdx.z;
    const int o2 = blockIdx.x * 256 + threadIdx.x;   // float2 column index
    if (o2 >= NWB2) return;

    const int d_begin = s ? HD_SPLIT : 0;
    const int d_end   = s ? HD       : HD_SPLIT;

    ull acc[2][4];   // [col j][batch-pair bp]
#pragma unroll
    for (int j = 0; j < 2; j++)
#pragma unroll
        for (int bp = 0; bp < 4; bp++) acc[j][bp] = 0ull;

    const float2*  w2p = reinterpret_cast<const float2*>(W2 + (size_t)g * HD * NWB);
    const double2* hp  = reinterpret_cast<const double2*>(g_h + (size_t)g * HD * Bsz);

    for (int d0 = d_begin; d0 < d_end; d0 += 4) {
        float2  w[4];
        double2 h0[4], h1[4];
#pragma unroll
        for (int u = 0; u < 4; u++) {
            w[u]  = __ldcs(w2p + (size_t)(d0 + u) * NWB2 + o2);
            h0[u] = __ldg(hp + (size_t)(d0 + u) * 2);
            h1[u] = __ldg(hp + (size_t)(d0 + u) * 2 + 1);
        }
#pragma unroll
        for (int u = 0; u < 4; u++) {
            const ull hb0 = __double_as_longlong(h0[u].x);   // (b0,b1)
            const ull hb1 = __double_as_longlong(h0[u].y);   // (b2,b3)
            const ull hb2 = __double_as_longlong(h1[u].x);   // (b4,b5)
            const ull hb3 = __double_as_longlong(h1[u].y);   // (b6,b7)
            const ull w0 = pack2(w[u].x, w[u].x);
            const ull w1 = pack2(w[u].y, w[u].y);
            fma2(acc[0][0], w0, hb0); fma2(acc[0][1], w0, hb1);
            fma2(acc[0][2], w0, hb2); fma2(acc[0][3], w0, hb3);
            fma2(acc[1][0], w1, hb0); fma2(acc[1][1], w1, hb1);
            fma2(acc[1][2], w1, hb2); fma2(acc[1][3], w1, hb3);
        }
    }

    float2 bv = make_float2(0.f, 0.f);
    if (s == 0) bv = reinterpret_cast<const float2*>(b2 + (size_t)g * NWB)[o2];

    float* base = g_part + (size_t)(s * Gn + g) * Bsz * NWB;
#pragma unroll
    for (int bp = 0; bp < 4; bp++) {
        const float2 c0 = unpack2(acc[0][bp]);   // col 2*o2   for batches 2bp,2bp+1
        const float2 c1 = unpack2(acc[1][bp]);   // col 2*o2+1
        reinterpret_cast<float2*>(base + (size_t)(2 * bp) * NWB)[o2] =
            make_float2(c0.x + bv.x, c1.x + bv.y);
        reinterpret_cast<float2*>(base + (size_t)(2 * bp + 1) * NWB)[o2] =
            make_float2(c0.y + bv.x, c1.y + bv.y);
    }
}

// ============================================================================
// Kernel 2.5: sum split-K partials + transpose weights to [g][b][cc][kk][oc]
// (contiguous per chunk) so conv can stage them with pure cp.async.
// Also sums biases into g_wb. Grid (CCH, G, B).
// ============================================================================
__global__ __launch_bounds__(256) void reduce_kernel()
{
    __shared__ float s[64 * 37];
    const int cc = blockIdx.x, g = blockIdx.y, b = blockIdx.z;
    const int tid = threadIdx.x;
    const float* p0 = g_part + ((size_t)(0 * Gn + g) * Bsz + b) * NWB;
    const float* p1 = g_part + ((size_t)(1 * Gn + g) * Bsz + b) * NWB;

    for (int idx = tid; idx < 64 * KKC; idx += 256) {
        const int oc = idx / KKC;
        const int kk = idx % KKC;                 // coalesced 144B runs
        const int gi = oc * 576 + cc * KKC + kk;
        s[oc * 37 + kk] = p0[gi] + p1[gi];
    }
    __syncthreads();

    float* dst = g_w + ((size_t)(g * Bsz + b) * CCH + cc) * W_BUF;
    for (int idx = tid; idx < 64 * KKC; idx += 256) {
        const int kk = idx >> 6;                  // idx / 64
        const int oc = idx & 63;
        dst[idx] = s[oc * 37 + kk];               // stride-37 -> conflict-free
    }
    if (cc == 0 && tid < 64)
        g_wb[(g * Bsz + b) * 64 + tid] = p0[NW + tid] + p1[NW + tid];
}

// ============================================================================
// Kernel 3: dynamic grouped 3x3 conv, cp.async double-buffered pipeline.
// 16 chunks of 4 input channels. Image rows stored at col offset 4 (16B
// aligned for cp.async); halo cols 3 / 68 and out-of-range rows stay zero
// (pre-zeroed once; pad positions identical for every chunk).
// Thread tile: 16 oc (8 f32x2 pairs) x 4 rows x 1 col. Per k-step:
// 8 broadcast LDS.64 + 4 LDS.32 + 4 pack + 32 fma2 = 52 issues / 64 fma-cyc.
// ============================================================================
__global__ __launch_bounds__(256, 2) void conv_kernel(
    const float* __restrict__ image,   // [B][256][64][64]
    float* __restrict__ out)           // [B][256][64][64]
{
    __shared__ __align__(16) float img_s[2][IMG_BUF];  // [buf][c*6+rr][72]
    __shared__ __align__(16) float w_s[2][W_BUF];      // [buf][kk][64]

    const int strip = blockIdx.x;
    const int g = blockIdx.y;
    const int b = blockIdx.z;
    const int tid = threadIdx.x;
    const int pid = tid & 63;
    const int ocg = tid >> 6;
    const int y0 = strip * 4;

    const float* img_base = image + (size_t)(b * 256 + g * 64) * 4096;
    const float* wt = g_w + (size_t)(g * Bsz + b) * CCH * W_BUF;

    // pre-zero image buffers (borders persist as zero across all chunks)
    for (int i = tid; i < 2 * IMG_BUF; i += 256)
        (&img_s[0][0])[i] = 0.f;
    __syncthreads();

    // ---- async stage of one chunk into buffer `buf` ----
    auto issue_chunk = [&](int cc, int buf) {
        // image: CPC*6 rows x 16 segments of 16B, interior cols only
        for (int k = tid; k < CPC * 6 * 16; k += 256) {
            const int row = k >> 4;               // 0..23: c*6+rr
            const int seg = k & 15;
            const int rr  = row % 6;
            const int c   = row / 6;
            const int yy  = y0 - 1 + rr;
            if (yy >= 0 && yy < 64) {
                uint32_t dst = (uint32_t)__cvta_generic_to_shared(
                    &img_s[buf][row * 72 + 4 + seg * 4]);
                cp16(dst, img_base + (size_t)(cc * CPC + c) * 4096 + yy * 64 + seg * 4);
            }
        }
        // weights: contiguous W_BUF floats
        const float* src = wt + (size_t)cc * W_BUF;
        for (int k = tid; k < W_BUF / 4; k += 256) {
            uint32_t dst = (uint32_t)__cvta_generic_to_shared(&w_s[buf][k * 4]);
            cp16(dst, src + k * 4);
        }
    };

    ull acc[8][4];
#pragma unroll
    for (int j = 0; j < 8; j++)
#pragma unroll
        for (int r = 0; r < 4; r++) acc[j][r] = 0ull;

    issue_chunk(0, 0);
    CP_COMMIT();

#pragma unroll 1
    for (int cc = 0; cc < CCH; cc++) {
        if (cc + 1 < CCH) { issue_chunk(cc + 1, (cc + 1) & 1); CP_COMMIT(); }
        if (cc + 1 < CCH) { CP_WAIT(1); } else { CP_WAIT(0); }
        __syncthreads();                       // publish arrived data to all warps

        const float* ib = img_s[cc & 1];
        const float* wb = w_s[cc & 1];
#pragma unroll 2
        for (int icl = 0; icl < CPC; icl++) {
#pragma unroll
            for (int p = 0; p < 9; p++) {
                const int kk = icl * 9 + p;
                const int dy = p / 3, dx = p % 3;
                ull vv[4];
#pragma unroll
                for (int r = 0; r < 4; r++) {
                    const float v = ib[(icl * 6 + r + dy) * 72 + 3 + pid + dx];
                    vv[r] = pack2(v, v);
                }
#pragma unroll
                for (int j = 0; j < 8; j++) {
                    const ull wv = *reinterpret_cast<const ull*>(
                        &wb[kk * 64 + ocg * 16 + 2 * j]);   // warp-broadcast
#pragma unroll
                    for (int r = 0; r < 4; r++) fma2(acc[j][r], wv, vv[r]);
                }
            }
        }
        __syncthreads();                       // compute done before buffer reuse
    }

    // ---- bias + writeout ----
    const float* bp = g_wb + (g * Bsz + b) * 64 + ocg * 16;
#pragma unroll
    for (int j = 0; j < 8; j++) {
        const float b0 = bp[2 * j], b1 = bp[2 * j + 1];
        const int oc0 = ocg * 16 + 2 * j;
#pragma unroll
        for (int r = 0; r < 4; r++) {
            const float2 rv = unpack2(acc[j][r]);
            const size_t base = ((size_t)(b * 256 + g * 64 + oc0) * 64 + (y0 + r)) * 64 + pid;
            out[base]        = rv.x + b0;
            out[base + 4096] = rv.y + b1;
        }
    }
}

// ============================================================================
// launch: [noop, noop, mlp1, mlp2, reduce, conv] — capture idx 3 = mlp2
// ============================================================================
extern "C" void kernel_launch(void* const* d_in, const int* in_sizes, int n_in,
                              void* d_out, int out_size) {
    const float* image = (const float*)d_in[0];
    const float* hyper = (const float*)d_in[1];
    const float* W1    = (const float*)d_in[2];
    const float* b1    = (const float*)d_in[3];
    const float* W2    = (const float*)d_in[4];
    const float* b2    = (const float*)d_in[5];
    float* out = (float*)d_out;

    noop_kernel<<<1, 32>>>();
    noop_kernel<<<1, 32>>>();
    mlp1_kernel<<<dim3(10, Gn, 4), 256>>>(hyper, W1, b1);
    mlp2_kernel<<<dim3(73, Gn, 2), 256>>>(W2, b2);         // ceil(18464/256)=73
    reduce_kernel<<<dim3(CCH, Gn, Bsz), 256>>>();
    conv_kernel<<<dim3(16, Gn, Bsz), 256>>>(image, out);
}